// round 14
// baseline (speedup 1.0000x reference)
#include <cuda_runtime.h>
#include <cuda.h>
#include <cuda_bf16.h>
#include <cstdint>

#define N_TOTAL 8388608   // 2^23

__device__ float2 g_scratch[N_TOTAL];   // transposed intermediate

__host__ __device__ __forceinline__ constexpr int brev_c(int x, int K) {
    int r = 0;
    for (int b = 0; b < K; b++) r |= ((x >> b) & 1) << (K - 1 - b);
    return r;
}

__device__ __forceinline__ float2 cmul(float2 a, float2 w) {
    return make_float2(a.x * w.x - a.y * w.y, a.x * w.y + a.y * w.x);
}

// Full-prefetch in-register DIF butterfly network, K stages at offset S0.
template <int S0, int K>
__device__ __forceinline__ void bnet_pf(float2* a, unsigned jj,
                                        const float2* __restrict__ W) {
    float2 tw[(1 << K) - 1];
#pragma unroll
    for (int u = 0; u < K; u++) {
#pragma unroll
        for (int c = 0; c < (1 << u); c++) {
            unsigned idx = (jj << (22 - S0 - u)) + ((unsigned)c << (22 - u));
            tw[(1 << u) - 1 + c] = __ldg(&W[idx]);
        }
    }
#pragma unroll
    for (int u = 0; u < K; u++) {
        const int half = 1 << (K - 1 - u);
#pragma unroll
        for (int t = 0; t < (1 << K) / 2; t++) {
            const int q1 = ((t & ~(half - 1)) << 1) | (t & (half - 1));
            const int q2 = q1 + half;
            const int c = brev_c(q1, K) & ((1 << u) - 1);
            float2 w = tw[(1 << u) - 1 + c];
            float2 p = cmul(a[q2], w);
            float2 tt = a[q1];
            a[q1] = make_float2(tt.x + p.x, tt.y + p.y);
            a[q2] = make_float2(tt.x - p.x, tt.y - p.y);
        }
    }
}

// ---- TMA / mbarrier helpers -------------------------------------------------
__device__ __forceinline__ uint32_t smem_u32(const void* p) {
    uint32_t a;
    asm("{ .reg .u64 t; cvta.to.shared.u64 t, %1; cvt.u32.u64 %0, t; }"
        : "=r"(a) : "l"(p));
    return a;
}
__device__ __forceinline__ void mbar_init(uint32_t mb, unsigned cnt) {
    asm volatile("mbarrier.init.shared.b64 [%0], %1;" :: "r"(mb), "r"(cnt)
                 : "memory");
}
__device__ __forceinline__ void mbar_expect(uint32_t mb, unsigned bytes) {
    asm volatile("mbarrier.arrive.expect_tx.shared.b64 _, [%0], %1;"
                 :: "r"(mb), "r"(bytes) : "memory");
}
__device__ __forceinline__ void mbar_wait0(uint32_t mb) {
    asm volatile(
        "{\n\t.reg .pred P;\n"
        "WL_%=:\n\t"
        "mbarrier.try_wait.parity.acquire.cta.shared::cta.b64 P, [%0], 0, 0x989680;\n\t"
        "@P bra.uni WD_%=;\n\t"
        "bra.uni WL_%=;\n"
        "WD_%=:\n\t}"
        :: "r"(mb) : "memory");
}
__device__ __forceinline__ void tma_load2d(const CUtensorMap* m, uint32_t dst,
                                           int cx, int cy, uint32_t mb) {
    asm volatile(
        "cp.async.bulk.tensor.2d.shared::cta.global.tile.mbarrier::complete_tx::bytes "
        "[%0], [%1, {%2, %3}], [%4];"
        :: "r"(dst), "l"(m), "r"(cx), "r"(cy), "r"(mb) : "memory");
}

// ============================================================================
// Kernel A: stages [0,11). Tile = 8 bases (g) x 2048 q, rounds 4+4+3 (R10).
// Input gather via 8 TMA 2D loads (box 8 f32 x 256 q) into a 64KB f32 stage;
// R1 reads stage[q*8+g] (lane-consecutive, conflict-free LDS.32).
// NO static smem: mbar carved from dynamic region (TMA needs 128B-aligned dst).
// Layout: [tile 131072B][stage 65536B][mbar slot 128B].
// ============================================================================
#define KA_SMEM_BYTES (16384 * 8 + 16384 * 4 + 128)

__device__ __forceinline__ unsigned phA(unsigned q, unsigned g) {
    unsigned l = (q << 3) | g;
    return l ^ (((l >> 6) & 1u) << 3);
}

__global__ void __launch_bounds__(512, 1)
fft_kA(const __grid_constant__ CUtensorMap tmap,
       const float2* __restrict__ W, float2* __restrict__ Yt) {
    extern __shared__ float2 sm2[];
    float* stage = reinterpret_cast<float*>(sm2 + 16384);        // +131072B
    uint32_t mb = smem_u32(sm2) + 16384u * 8u + 16384u * 4u;     // +196608B

    const unsigned t = threadIdx.x;
    const unsigned g = t & 7u;
    const unsigned rest = t >> 3;

    if (t == 0) mbar_init(mb, 1);
    __syncthreads();
    if (t == 0) {
        mbar_expect(mb, 16384 * 4);
        uint32_t sa = smem_u32(stage);
#pragma unroll
        for (int k = 0; k < 8; k++)
            tma_load2d(&tmap, sa + (unsigned)k * 8192u,
                       (int)(blockIdx.x * 8u), k * 256, mb);
    }
    mbar_wait0(mb);

    // round 1: bits q[10:7], S0=0, jj=0; data from staging tile (imag=0)
#pragma unroll
    for (int pass = 0; pass < 2; pass++) {
        unsigned low7 = rest + 64u * pass;
        float2 a[16];
#pragma unroll
        for (int x = 0; x < 16; x++) {
            unsigned q = ((unsigned)x << 7) | low7;
            a[x] = make_float2(stage[q * 8u + g], 0.0f);
        }
        bnet_pf<0, 4>(a, 0u, W);
#pragma unroll
        for (int x = 0; x < 16; x++)
            sm2[phA(((unsigned)x << 7) | low7, g)] = a[x];
    }
    __syncthreads();

    // round 2: bits q[6:3], S0=4, jj = brev4(q[10:7])
#pragma unroll
    for (int pass = 0; pass < 2; pass++) {
        unsigned idx2 = rest + 64u * pass;
        unsigned lo3 = idx2 & 7u;
        unsigned H = idx2 >> 3;
        unsigned jj = __brev(H) >> 28;
        float2 a[16];
#pragma unroll
        for (int x = 0; x < 16; x++)
            a[x] = sm2[phA((H << 7) | ((unsigned)x << 3) | lo3, g)];
        bnet_pf<4, 4>(a, jj, W);
#pragma unroll
        for (int x = 0; x < 16; x++)
            sm2[phA((H << 7) | ((unsigned)x << 3) | lo3, g)] = a[x];
    }
    __syncthreads();

    // round 3: bits q[2:0], S0=8, K=3, jj = brev8(q[10:3]); write transposed
    const unsigned base = blockIdx.x * 8u + g;
#pragma unroll
    for (int pass = 0; pass < 4; pass++) {
        unsigned B = rest + 64u * pass;
        unsigned jj = __brev(B) >> 24;
        float2 a[8];
#pragma unroll
        for (int x = 0; x < 8; x++)
            a[x] = sm2[phA((B << 3) | (unsigned)x, g)];
        bnet_pf<8, 3>(a, jj, W);
#pragma unroll
        for (int x = 0; x < 8; x++) {
            unsigned C = ((unsigned)brev_c(x, 3) << 8) | jj;
            Yt[C * 4096u + base] = a[x];
        }
    }
}

// ============================================================================
// Kernel B: stages [11,23). Tile = 4 j x 4096 q, rounds 4+4+4 (R10).
// Tile loaded by 32 TMA 2D loads (box 256 f32 x 4 j) in box-major order:
//   f2 element (jg,q) at smem index s = (q>>7)*512 + jg*128 + (q&127).
// R1: read box layout, net, barrier, in-place relayout into phB swizzle.
// Layout: [tile 131072B][mbar slot 128B]. R2/R3 = R10-exact.
// ============================================================================
#define KB_SMEM_BYTES (16384 * 8 + 128)

__device__ __forceinline__ unsigned phB(unsigned q, unsigned js) {
    unsigned l = (q << 2) | js;
    return l ^ ((l >> 4) & 3u) ^ (((l >> 6) & 3u) << 2);
}

__global__ void __launch_bounds__(512, 1)
fft_kB(const __grid_constant__ CUtensorMap tmap,
       const float2* __restrict__ W, float2* __restrict__ Out) {
    extern __shared__ float2 sm2[];
    uint32_t mb = smem_u32(sm2) + 16384u * 8u;

    const unsigned t = threadIdx.x;
    const unsigned j0 = blockIdx.x * 4u;

    if (t == 0) mbar_init(mb, 1);
    __syncthreads();
    if (t == 0) {
        mbar_expect(mb, 16384 * 8);
        uint32_t sa = smem_u32(sm2);
#pragma unroll
        for (int k = 0; k < 32; k++)
            tma_load2d(&tmap, sa + (unsigned)k * 4096u,
                       k * 256, (int)j0, mb);
    }
    mbar_wait0(mb);

    // round 1: bits q[11:8], S0=11. jg1 = t>>7 (warp-uniform jB).
    {
        const unsigned jg1 = t >> 7;
        const unsigned lowt = t & 127u;
        const unsigned jB1 = j0 + jg1;
        float2 a[2][16];
#pragma unroll
        for (int pass = 0; pass < 2; pass++) {
            unsigned low8 = lowt + 128u * pass;
#pragma unroll
            for (int x = 0; x < 16; x++) {
                unsigned q = ((unsigned)x << 8) | low8;
                unsigned s = ((q >> 7) << 9) | (jg1 << 7) | (q & 127u);
                a[pass][x] = sm2[s];
            }
        }
#pragma unroll
        for (int pass = 0; pass < 2; pass++)
            bnet_pf<11, 4>(a[pass], jB1, W);
        __syncthreads();   // all box-layout reads done -> safe to overwrite
#pragma unroll
        for (int pass = 0; pass < 2; pass++) {
            unsigned low8 = lowt + 128u * pass;
#pragma unroll
            for (int x = 0; x < 16; x++)
                sm2[phB(((unsigned)x << 8) | low8, jg1)] = a[pass][x];
        }
    }
    __syncthreads();

    const unsigned jg = t & 3u;
    const unsigned rest = t >> 2;
    const unsigned jB = j0 + jg;

    // round 2: bits q[7:4], S0=15, jj = jB + brev4(q[11:8])<<11
#pragma unroll
    for (int pass = 0; pass < 2; pass++) {
        unsigned idx2 = rest + 128u * pass;
        unsigned lo4 = idx2 & 15u;
        unsigned H = idx2 >> 4;
        unsigned jj = jB + ((__brev(H) >> 28) << 11);
        float2 a[16];
#pragma unroll
        for (int x = 0; x < 16; x++)
            a[x] = sm2[phB((H << 8) | ((unsigned)x << 4) | lo4, jg)];
        bnet_pf<15, 4>(a, jj, W);
#pragma unroll
        for (int x = 0; x < 16; x++)
            sm2[phB((H << 8) | ((unsigned)x << 4) | lo4, jg)] = a[x];
    }
    __syncthreads();

    // round 3: bits q[3:0], S0=19, jj = jB + brev8(q[11:4])<<11; write out
#pragma unroll
    for (int pass = 0; pass < 2; pass++) {
        unsigned B = rest + 128u * pass;
        unsigned Brev = __brev(B) >> 24;
        unsigned jj = jB + (Brev << 11);
        float2 a[16];
#pragma unroll
        for (int x = 0; x < 16; x++)
            a[x] = sm2[phB((B << 4) | (unsigned)x, jg)];
        bnet_pf<19, 4>(a, jj, W);
#pragma unroll
        for (int x = 0; x < 16; x++) {
            unsigned C = ((unsigned)brev_c(x, 4) << 8) | Brev;
            __stcs(&Out[(C << 11) + jB], a[x]);
        }
    }
}

// ---------------------------------------------------------------------------
typedef CUresult (*EncodeFn)(
    CUtensorMap*, CUtensorMapDataType, cuuint32_t, void*,
    const cuuint64_t*, const cuuint64_t*, const cuuint32_t*, const cuuint32_t*,
    CUtensorMapInterleave, CUtensorMapSwizzle, CUtensorMapL2promotion,
    CUtensorMapFloatOOBfill);

static void make_map(EncodeFn enc, CUtensorMap* m, void* ptr,
                     cuuint64_t d0, cuuint64_t d1, cuuint64_t strideB,
                     cuuint32_t b0, cuuint32_t b1) {
    cuuint64_t gd[2] = {d0, d1};
    cuuint64_t gs[1] = {strideB};
    cuuint32_t bx[2] = {b0, b1};
    cuuint32_t es[2] = {1, 1};
    enc(m, CU_TENSOR_MAP_DATA_TYPE_FLOAT32, 2, ptr, gd, gs, bx, es,
        CU_TENSOR_MAP_INTERLEAVE_NONE, CU_TENSOR_MAP_SWIZZLE_NONE,
        CU_TENSOR_MAP_L2_PROMOTION_L2_128B, CU_TENSOR_MAP_FLOAT_OOB_FILL_NONE);
}

extern "C" void kernel_launch(void* const* d_in, const int* in_sizes, int n_in,
                              void* d_out, int out_size) {
    void* inp = d_in[0];
    const float2* w = (const float2*)d_in[1];
    float2* out = (float2*)d_out;

    float2* scr = nullptr;
    cudaGetSymbolAddress((void**)&scr, g_scratch);

    static EncodeFn enc = nullptr;
    if (!enc) {
        void* p = nullptr;
        cudaDriverEntryPointQueryResult qr;
        cudaGetDriverEntryPoint("cuTensorMapEncodeTiled", &p,
                                cudaEnableDefault, &qr);
        enc = (EncodeFn)p;
    }

    // kA input map: f32 [base=4096 cols][q=2048 rows], box (8 base, 256 q)
    CUtensorMap mapA;
    make_map(enc, &mapA, inp, 4096, 2048, 4096ull * 4ull, 8, 256);

    // kB scratch map: f32 [8192 f32 per row][j=2048 rows], box (256, 4)
    CUtensorMap mapB;
    make_map(enc, &mapB, scr, 8192, 2048, 8192ull * 4ull, 256, 4);

    cudaFuncSetAttribute(fft_kA, cudaFuncAttributeMaxDynamicSharedMemorySize,
                         KA_SMEM_BYTES);
    cudaFuncSetAttribute(fft_kB, cudaFuncAttributeMaxDynamicSharedMemorySize,
                         KB_SMEM_BYTES);

    fft_kA<<<512, 512, KA_SMEM_BYTES>>>(mapA, w, scr);   // stages 0..10
    fft_kB<<<512, 512, KB_SMEM_BYTES>>>(mapB, w, out);   // stages 11..22
}